// round 5
// baseline (speedup 1.0000x reference)
#include <cuda_runtime.h>
#include <cuda_bf16.h>
#include <cstddef>

// RNN_5188320494079: N=64, T=1024, D=256, H=256, all fp32.
// Inputs: x[N,T,D], h0[N,H], Wx[D,H], Wh[H,H], b[H].  Output: [N,T,H].
//
// Kernel 1: Out[n,t,:] = x[n,t,:] @ Wx + b  (parallel GEMM, in-place into d_out)
// Kernel 2: 64 CTAs (one per n), sequential in-place scan:
//           h_t = tanh(Out[n,t,:] + h_{t-1} @ Wh);  Out[n,t,:] = h_t
//
// Both kernels use Blackwell packed fp32 FMA (fma.rn.f32x2) to halve the
// FFMA instruction count — R4 profiling showed the scan is issue-bound
// (~87% issue_active on active SMs).

#define RNN_N 64
#define RNN_T 1024
#define RNN_D 256
#define RNN_H 256

typedef unsigned long long ull;

// d = a * b + d, elementwise on packed {f32,f32}. Bitwise == two fma.rn.f32.
__device__ __forceinline__ void ffma2(ull& d, ull a, ull b) {
    asm("fma.rn.f32x2 %0, %1, %2, %0;" : "+l"(d) : "l"(a), "l"(b));
}
__device__ __forceinline__ float2 u2f(ull u) {
    float2 f;
    asm("mov.b64 {%0, %1}, %2;" : "=f"(f.x), "=f"(f.y) : "l"(u));
    return f;
}

// ---------------------------------------------------------------------------
// Kernel 1: smem-tiled SGEMM with packed-f32x2 micro-kernel.
// BM=128 BN=128 BK=16, 256 threads, 8x8 micro tile (as 8 i x 4 j-pairs).
// A is stored DUPLICATED in smem (float2{a,a}) so the packed a-operand is a
// direct LDS; B pairs {b_j, b_j+1} are naturally adjacent.
// M = N*T = 65536, K = 256, Ncols = 256. Grid (512, 2).
// ---------------------------------------------------------------------------
__global__ __launch_bounds__(256, 2)
void gemm_xw_kernel(const float* __restrict__ X, const float* __restrict__ Wx,
                    const float* __restrict__ bias, float* __restrict__ Out) {
    __shared__ __align__(16) float2 Asd[16][128];  // [k][m] duplicated {a,a}, 16KB
    __shared__ __align__(16) float  Bs[16][128];   // [k][n], 8KB

    const int tid = threadIdx.x;
    const int tx = tid & 15;        // output col group (8 cols = 4 pairs)
    const int ty = tid >> 4;        // output row group (8 rows)
    const int m0 = blockIdx.x * 128;
    const int n0 = blockIdx.y * 128;

    const int a_row = tid >> 2;          // 0..63
    const int a_col = (tid & 3) << 2;    // 0,4,8,12
    const int b_row = tid >> 5;          // 0..7
    const int b_col = (tid & 31) << 2;   // 0..124

    ull acc[8][4];
#pragma unroll
    for (int i = 0; i < 8; i++)
#pragma unroll
        for (int j = 0; j < 4; j++) acc[i][j] = 0ull;

    const float* Xa0 = &X[(size_t)(m0 + a_row) * RNN_D + a_col];
    const float* Xa1 = &X[(size_t)(m0 + a_row + 64) * RNN_D + a_col];
    const float* Wb0 = &Wx[(size_t)b_row * RNN_H + n0 + b_col];
    const float* Wb1 = &Wx[(size_t)(b_row + 8) * RNN_H + n0 + b_col];

    for (int k0 = 0; k0 < RNN_D; k0 += 16) {
        float4 av0 = __ldcs(reinterpret_cast<const float4*>(Xa0 + k0));
        float4 av1 = __ldcs(reinterpret_cast<const float4*>(Xa1 + k0));
        float4 bv0 = *reinterpret_cast<const float4*>(Wb0 + (size_t)k0 * RNN_H);
        float4 bv1 = *reinterpret_cast<const float4*>(Wb1 + (size_t)k0 * RNN_H);
        __syncthreads();   // previous tile fully consumed
        Asd[a_col + 0][a_row] = make_float2(av0.x, av0.x);
        Asd[a_col + 1][a_row] = make_float2(av0.y, av0.y);
        Asd[a_col + 2][a_row] = make_float2(av0.z, av0.z);
        Asd[a_col + 3][a_row] = make_float2(av0.w, av0.w);
        Asd[a_col + 0][a_row + 64] = make_float2(av1.x, av1.x);
        Asd[a_col + 1][a_row + 64] = make_float2(av1.y, av1.y);
        Asd[a_col + 2][a_row + 64] = make_float2(av1.z, av1.z);
        Asd[a_col + 3][a_row + 64] = make_float2(av1.w, av1.w);
        *reinterpret_cast<float4*>(&Bs[b_row][b_col]) = bv0;
        *reinterpret_cast<float4*>(&Bs[b_row + 8][b_col]) = bv1;
        __syncthreads();
#pragma unroll
        for (int k = 0; k < 16; k++) {
            const ulonglong2* ad = reinterpret_cast<const ulonglong2*>(&Asd[k][ty * 8]);
            ulonglong2 aa0 = ad[0], aa1 = ad[1], aa2 = ad[2], aa3 = ad[3];
            const ulonglong2* bd = reinterpret_cast<const ulonglong2*>(&Bs[k][tx * 8]);
            ulonglong2 bb0 = bd[0], bb1 = bd[1];
            ull ap[8] = {aa0.x, aa0.y, aa1.x, aa1.y, aa2.x, aa2.y, aa3.x, aa3.y};
            ull bp[4] = {bb0.x, bb0.y, bb1.x, bb1.y};
#pragma unroll
            for (int i = 0; i < 8; i++) {
                ffma2(acc[i][0], ap[i], bp[0]);
                ffma2(acc[i][1], ap[i], bp[1]);
                ffma2(acc[i][2], ap[i], bp[2]);
                ffma2(acc[i][3], ap[i], bp[3]);
            }
        }
    }

    float4 bb0 = *reinterpret_cast<const float4*>(&bias[n0 + tx * 8]);
    float4 bb1 = *reinterpret_cast<const float4*>(&bias[n0 + tx * 8 + 4]);
    float bb[8] = {bb0.x, bb0.y, bb0.z, bb0.w, bb1.x, bb1.y, bb1.z, bb1.w};
#pragma unroll
    for (int i = 0; i < 8; i++) {
        size_t r = (size_t)(m0 + ty * 8 + i) * RNN_H + n0 + tx * 8;
        float2 v0 = u2f(acc[i][0]), v1 = u2f(acc[i][1]);
        float2 v2 = u2f(acc[i][2]), v3 = u2f(acc[i][3]);
        float4 o0 = make_float4(v0.x + bb[0], v0.y + bb[1], v1.x + bb[2], v1.y + bb[3]);
        float4 o1 = make_float4(v2.x + bb[4], v2.y + bb[5], v3.x + bb[6], v3.y + bb[7]);
        *reinterpret_cast<float4*>(&Out[r]) = o0;
        *reinterpret_cast<float4*>(&Out[r + 4]) = o1;
    }
}

// ---------------------------------------------------------------------------
// Kernel 2: recurrence scan. 64 CTAs (one per batch n), 512 threads.
// Thread (q = tid>>6, jg = tid&63) computes partial[j] over its 32-row octant
// for j-pairs {4jg,4jg+1},{4jg+2,4jg+3} with packed FFMA2:
//   - rows ibase..ibase+23: Wh pairs held in 96 registers (loaded once)
//   - rows ibase+24..+31:   Wh streamed from an L1-resident 64KB slice
//   - h kept DUPLICATED in smem as float2{h,h} -> packed a-operand is a
//     single broadcast LDS.128 for two rows (no pack instructions)
//   - 8 partials reduced via smem; xw_{t+1} prefetched with __ldcg; h stored
//     __stcs, overwriting the xW slot in d_out.
// ---------------------------------------------------------------------------
__global__ __launch_bounds__(512, 1)
void rnn_scan_kernel(const float* __restrict__ h0,
                     const float* __restrict__ Wh,
                     float* Out) {
    __shared__ __align__(16) float2 hdup[2][RNN_H];  // {h,h} duplicated, 4KB
    __shared__ __align__(16) float  Psm[8][RNN_H];   // octant partials, 8KB

    const int tid = threadIdx.x;
    const int n = blockIdx.x;
    const int jg = tid & 63;       // j-group of 4 (warp-contiguous -> coalesced)
    const int q = tid >> 6;        // i-octant (warp-uniform -> broadcast h loads)
    const int j4 = jg * 4;
    const int ibase = q * 32;

    // Register Wh tile: rows ibase..ibase+23, packed as j-pairs (96 regs).
    ull wr[24][2];
#pragma unroll
    for (int k = 0; k < 24; k++) {
        ulonglong2 wv = *reinterpret_cast<const ulonglong2*>(
            &Wh[(size_t)(ibase + k) * RNN_H + j4]);
        wr[k][0] = wv.x; wr[k][1] = wv.y;
    }
    // L1-streamed remainder rows ibase+24..ibase+31; row stride = 64 ulonglong2.
    const ulonglong2* WhT2 = reinterpret_cast<const ulonglong2*>(
        &Wh[(size_t)(ibase + 24) * RNN_H + j4]);

    float* outp = Out + (size_t)n * RNN_T * RNN_H;
    float xw_cur = 0.f, xw_nxt = 0.f;
    if (tid < RNN_H) {
        float hv = h0[(size_t)n * RNN_H + tid];
        hdup[0][tid] = make_float2(hv, hv);
        xw_cur = __ldcg(&outp[tid]);            // xW at t=0 (from kernel 1)
    }
    __syncthreads();

    int cur = 0;
    for (int t = 0; t < RNN_T; t++) {
        // prefetch next timestep's xW (L2 path; no L1 pollution of Wh slice)
        if (tid < RNN_H && t + 1 < RNN_T)
            xw_nxt = __ldcg(&outp[RNN_H + tid]);

        const ulonglong2* hdp =
            reinterpret_cast<const ulonglong2*>(&hdup[cur][ibase]);
        ull a01 = 0ull, a23 = 0ull;

        // register-Wh part: 24 rows, 12 broadcast LDS.128 (2 dup-h each)
#pragma unroll
        for (int m = 0; m < 12; m++) {
            ulonglong2 hp = hdp[m];
            ffma2(a01, hp.x, wr[2 * m][0]);     ffma2(a23, hp.x, wr[2 * m][1]);
            ffma2(a01, hp.y, wr[2 * m + 1][0]); ffma2(a23, hp.y, wr[2 * m + 1][1]);
        }
        // L1-Wh part: 8 rows
#pragma unroll
        for (int m = 0; m < 4; m++) {
            ulonglong2 hp = hdp[12 + m];
            ulonglong2 w0 = __ldg(&WhT2[(size_t)(2 * m) * 64]);
            ulonglong2 w1 = __ldg(&WhT2[(size_t)(2 * m + 1) * 64]);
            ffma2(a01, hp.x, w0.x); ffma2(a23, hp.x, w0.y);
            ffma2(a01, hp.y, w1.x); ffma2(a23, hp.y, w1.y);
        }

        ulonglong2 pp; pp.x = a01; pp.y = a23;
        *reinterpret_cast<ulonglong2*>(&Psm[q][j4]) = pp;
        __syncthreads();

        if (tid < RNN_H) {
            float z = xw_cur;
#pragma unroll
            for (int qq = 0; qq < 8; qq++) z += Psm[qq][tid];
            float hn = tanhf(z);
            hdup[cur ^ 1][tid] = make_float2(hn, hn);
            __stcs(&outp[tid], hn);   // overwrite xW slot with h_t
            xw_cur = xw_nxt;
        }
        __syncthreads();   // h_{t+1} visible; Psm free for reuse
        cur ^= 1;
        outp += RNN_H;
    }
}

// ---------------------------------------------------------------------------
extern "C" void kernel_launch(void* const* d_in, const int* in_sizes, int n_in,
                              void* d_out, int out_size) {
    const float* x  = (const float*)d_in[0];   // [N,T,D]
    const float* h0 = (const float*)d_in[1];   // [N,H]
    const float* Wx = (const float*)d_in[2];   // [D,H]
    const float* Wh = (const float*)d_in[3];   // [H,H]
    const float* b  = (const float*)d_in[4];   // [H]
    float* out = (float*)d_out;                // [N,T,H]

    (void)in_sizes; (void)n_in; (void)out_size;

    dim3 g1((RNN_N * RNN_T) / 128, RNN_H / 128);
    gemm_xw_kernel<<<g1, 256>>>(x, Wx, b, out);

    rnn_scan_kernel<<<RNN_N, 512>>>(h0, Wh, out);
}

// round 6
// speedup vs baseline: 1.8291x; 1.8291x over previous
#include <cuda_runtime.h>
#include <cuda_bf16.h>
#include <cstdint>
#include <cstddef>

// RNN_5188320494079: N=64, T=1024, D=256, H=256, fp32.
// Inputs: x[N,T,D], h0[N,H], Wx[D,H], Wh[H,H], b[H]. Output: [N,T,H].
//
// Kernel 1: Out = x @ Wx + b (packed-f32x2 SGEMM, in-place into d_out).
// Kernel 2: 2-CTA-cluster scan, 128 CTAs (2 per batch). Each CTA owns 128
//           output columns with its 256x128 Wh slice FULLY register-resident
//           (64 regs/thread across 512 threads). Halves of h are exchanged
//           per step via DSMEM store + mbarrier release/acquire handshake.

#define RNN_N 64
#define RNN_T 1024
#define RNN_D 256
#define RNN_H 256
#define HHALF 128

typedef unsigned long long ull;

// packed {f32,f32} fma: d = a*b + d  (bitwise == two fma.rn.f32)
__device__ __forceinline__ void ffma2(ull& d, ull a, ull b) {
    asm("fma.rn.f32x2 %0, %1, %2, %0;" : "+l"(d) : "l"(a), "l"(b));
}
__device__ __forceinline__ float2 u2f(ull u) {
    float2 f;
    asm("mov.b64 {%0, %1}, %2;" : "=f"(f.x), "=f"(f.y) : "l"(u));
    return f;
}
__device__ __forceinline__ uint32_t smem_u32(const void* p) {
    uint32_t a;
    asm("{ .reg .u64 t; cvta.to.shared.u64 t, %1; cvt.u32.u64 %0, t; }"
        : "=r"(a) : "l"(p));
    return a;
}

// ---------------------------------------------------------------------------
// Kernel 1: smem-tiled SGEMM, BM=128 BN=128 BK=16, 256 thr, f32x2 micro-kernel.
// A duplicated in smem ({a,a}) so packed a-operand is a direct LDS.
// ---------------------------------------------------------------------------
__global__ __launch_bounds__(256, 2)
void gemm_xw_kernel(const float* __restrict__ X, const float* __restrict__ Wx,
                    const float* __restrict__ bias, float* __restrict__ Out) {
    __shared__ __align__(16) float2 Asd[16][128];
    __shared__ __align__(16) float  Bs[16][128];

    const int tid = threadIdx.x;
    const int tx = tid & 15;
    const int ty = tid >> 4;
    const int m0 = blockIdx.x * 128;
    const int n0 = blockIdx.y * 128;

    const int a_row = tid >> 2;
    const int a_col = (tid & 3) << 2;
    const int b_row = tid >> 5;
    const int b_col = (tid & 31) << 2;

    ull acc[8][4];
#pragma unroll
    for (int i = 0; i < 8; i++)
#pragma unroll
        for (int j = 0; j < 4; j++) acc[i][j] = 0ull;

    const float* Xa0 = &X[(size_t)(m0 + a_row) * RNN_D + a_col];
    const float* Xa1 = &X[(size_t)(m0 + a_row + 64) * RNN_D + a_col];
    const float* Wb0 = &Wx[(size_t)b_row * RNN_H + n0 + b_col];
    const float* Wb1 = &Wx[(size_t)(b_row + 8) * RNN_H + n0 + b_col];

    for (int k0 = 0; k0 < RNN_D; k0 += 16) {
        float4 av0 = __ldcs(reinterpret_cast<const float4*>(Xa0 + k0));
        float4 av1 = __ldcs(reinterpret_cast<const float4*>(Xa1 + k0));
        float4 bv0 = *reinterpret_cast<const float4*>(Wb0 + (size_t)k0 * RNN_H);
        float4 bv1 = *reinterpret_cast<const float4*>(Wb1 + (size_t)k0 * RNN_H);
        __syncthreads();
        Asd[a_col + 0][a_row] = make_float2(av0.x, av0.x);
        Asd[a_col + 1][a_row] = make_float2(av0.y, av0.y);
        Asd[a_col + 2][a_row] = make_float2(av0.z, av0.z);
        Asd[a_col + 3][a_row] = make_float2(av0.w, av0.w);
        Asd[a_col + 0][a_row + 64] = make_float2(av1.x, av1.x);
        Asd[a_col + 1][a_row + 64] = make_float2(av1.y, av1.y);
        Asd[a_col + 2][a_row + 64] = make_float2(av1.z, av1.z);
        Asd[a_col + 3][a_row + 64] = make_float2(av1.w, av1.w);
        *reinterpret_cast<float4*>(&Bs[b_row][b_col]) = bv0;
        *reinterpret_cast<float4*>(&Bs[b_row + 8][b_col]) = bv1;
        __syncthreads();
#pragma unroll
        for (int k = 0; k < 16; k++) {
            const ulonglong2* ad = reinterpret_cast<const ulonglong2*>(&Asd[k][ty * 8]);
            ulonglong2 aa0 = ad[0], aa1 = ad[1], aa2 = ad[2], aa3 = ad[3];
            const ulonglong2* bd = reinterpret_cast<const ulonglong2*>(&Bs[k][tx * 8]);
            ulonglong2 bb0 = bd[0], bb1 = bd[1];
            ull ap[8] = {aa0.x, aa0.y, aa1.x, aa1.y, aa2.x, aa2.y, aa3.x, aa3.y};
            ull bp[4] = {bb0.x, bb0.y, bb1.x, bb1.y};
#pragma unroll
            for (int i = 0; i < 8; i++) {
                ffma2(acc[i][0], ap[i], bp[0]);
                ffma2(acc[i][1], ap[i], bp[1]);
                ffma2(acc[i][2], ap[i], bp[2]);
                ffma2(acc[i][3], ap[i], bp[3]);
            }
        }
    }

    float4 bb0 = *reinterpret_cast<const float4*>(&bias[n0 + tx * 8]);
    float4 bb1 = *reinterpret_cast<const float4*>(&bias[n0 + tx * 8 + 4]);
    float bb[8] = {bb0.x, bb0.y, bb0.z, bb0.w, bb1.x, bb1.y, bb1.z, bb1.w};
#pragma unroll
    for (int i = 0; i < 8; i++) {
        size_t r = (size_t)(m0 + ty * 8 + i) * RNN_H + n0 + tx * 8;
        float2 v0 = u2f(acc[i][0]), v1 = u2f(acc[i][1]);
        float2 v2 = u2f(acc[i][2]), v3 = u2f(acc[i][3]);
        float4 o0 = make_float4(v0.x + bb[0], v0.y + bb[1], v1.x + bb[2], v1.y + bb[3]);
        float4 o1 = make_float4(v2.x + bb[4], v2.y + bb[5], v3.x + bb[6], v3.y + bb[7]);
        *reinterpret_cast<float4*>(&Out[r]) = o0;
        *reinterpret_cast<float4*>(&Out[r + 4]) = o1;
    }
}

// ---------------------------------------------------------------------------
// Kernel 2: cluster scan. Grid = 128 CTAs, cluster (2,1,1): cluster c = batch n,
// rank r owns output columns [r*128, r*128+128).
// Thread layout (512 thr): jg = tid&31 -> 4 local cols; q = tid>>5 -> 16 i-rows.
// Wh slice (16 rows x 4 cols per thread) fully in registers as 32 j-pairs.
// Per step:
//   threads whose i-rows belong to the PEER half wait (acquire.cluster) on the
//   local mbarrier for the peer's h-half; own-half threads proceed immediately.
//   32 FFMA2 per thread -> Psm[16][128] -> 128 threads reduce + tanh -> write
//   h-half locally + DSMEM store to peer + release arrive on peer's mbarrier.
// ---------------------------------------------------------------------------
__global__ __launch_bounds__(512, 1) __cluster_dims__(2, 1, 1)
void rnn_scan_kernel(const float* __restrict__ h0,
                     const float* __restrict__ Wh,
                     float* Out) {
    __shared__ __align__(16) float2 hdup[2][RNN_H];   // {h,h} duplicated, 4KB
    __shared__ __align__(16) float  Psm[16][HHALF];   // partials, 8KB
    __shared__ __align__(8)  unsigned long long mbar; // peer-half-ready barrier

    const int tid = threadIdx.x;
    uint32_t rank;
    asm("mov.u32 %0, %%cluster_ctarank;" : "=r"(rank));
    const uint32_t peer = rank ^ 1u;
    const int n = blockIdx.x >> 1;
    const int jg = tid & 31;
    const int q = tid >> 5;
    const int jl4 = jg * 4;
    const int jglob4 = (int)rank * HHALF + jl4;
    const int ibase = q * 16;
    // h entries [0,128) are produced by rank 0, [128,256) by rank 1.
    const bool needs_peer = ((uint32_t)(ibase >> 7) != rank);

    const uint32_t hdup_base = smem_u32(hdup);
    const uint32_t mbar_addr = smem_u32((const void*)&mbar);

    if (tid == 0) {
        asm volatile("mbarrier.init.shared.b64 [%0], %1;"
                     :: "r"(mbar_addr), "r"(HHALF) : "memory");
    }
    __syncthreads();
    // all mbarriers initialized cluster-wide before any remote arrive
    asm volatile("barrier.cluster.arrive.aligned;" ::: "memory");
    asm volatile("barrier.cluster.wait.aligned;" ::: "memory");

    // Register-resident Wh slice: rows ibase..ibase+15, cols jglob4..jglob4+3.
    ull wr[16][2];
#pragma unroll
    for (int k = 0; k < 16; k++) {
        ulonglong2 wv = *reinterpret_cast<const ulonglong2*>(
            &Wh[(size_t)(ibase + k) * RNN_H + jglob4]);
        wr[k][0] = wv.x; wr[k][1] = wv.y;
    }

    float* outn = Out + (size_t)n * RNN_T * RNN_H;
    const int gcol = (int)rank * HHALF + tid;   // output column (tid<128 only)
    float xw_cur = 0.f, xw_nxt = 0.f;
    if (tid < RNN_H) {
        float hv = h0[(size_t)n * RNN_H + tid];
        hdup[0][tid] = make_float2(hv, hv);
    }
    uint32_t my_h_addr0 = 0, my_h_addr1 = 0;
    if (tid < HHALF) {
        xw_cur = __ldcg(&outn[gcol]);
        my_h_addr0 = hdup_base + (uint32_t)(0 * RNN_H + gcol) * 8u;
        my_h_addr1 = hdup_base + (uint32_t)(1 * RNN_H + gcol) * 8u;
    }
    __syncthreads();

    int cur = 0;
    for (int t = 0; t < RNN_T; t++) {
        if (tid < HHALF && t + 1 < RNN_T)
            xw_nxt = __ldcg(&outn[(size_t)(t + 1) * RNN_H + gcol]);

        // Wait for peer's h-half (steps t>=1). Own-half threads skip: the
        // exchange latency overlaps their FFMA2 work.
        if (needs_peer && t > 0) {
            uint32_t wpar = (uint32_t)(t - 1) & 1u;
            asm volatile(
                "{\n\t.reg .pred P;\n\t"
                "WL%=:\n\t"
                "mbarrier.try_wait.parity.acquire.cluster.shared::cta.b64 P, [%0], %1, 0x989680;\n\t"
                "@P bra.uni WD%=;\n\t"
                "bra.uni WL%=;\n\t"
                "WD%=:\n\t}"
                :: "r"(mbar_addr), "r"(wpar) : "memory");
        }

        const ulonglong2* hdp =
            reinterpret_cast<const ulonglong2*>(&hdup[cur][ibase]);
        ull a01 = 0ull, a23 = 0ull;
#pragma unroll
        for (int m = 0; m < 8; m++) {
            ulonglong2 hp = hdp[m];     // broadcast LDS.128: 2 dup'd h values
            ffma2(a01, hp.x, wr[2 * m][0]);     ffma2(a23, hp.x, wr[2 * m][1]);
            ffma2(a01, hp.y, wr[2 * m + 1][0]); ffma2(a23, hp.y, wr[2 * m + 1][1]);
        }
        ulonglong2 pp; pp.x = a01; pp.y = a23;
        *reinterpret_cast<ulonglong2*>(&Psm[q][jl4]) = pp;
        __syncthreads();

        const int nxt = cur ^ 1;
        if (tid < HHALF) {
            float z = xw_cur;
#pragma unroll
            for (int qq = 0; qq < 16; qq++) z += Psm[qq][tid];
            float hn = tanhf(z);
            hdup[nxt][gcol] = make_float2(hn, hn);           // local copy
            ull hpk; asm("mov.b64 %0, {%1, %1};" : "=l"(hpk) : "f"(hn));
            uint32_t la = nxt ? my_h_addr1 : my_h_addr0;
            asm volatile(                                     // peer copy (DSMEM)
                "{\n\t.reg .b32 ra;\n\t"
                "mapa.shared::cluster.u32 ra, %0, %1;\n\t"
                "st.shared::cluster.b64 [ra], %2;\n\t}"
                :: "r"(la), "r"(peer), "l"(hpk) : "memory");
            asm volatile(                                     // release arrive
                "{\n\t.reg .b32 rb;\n\t"
                "mapa.shared::cluster.u32 rb, %0, %1;\n\t"
                "mbarrier.arrive.release.cluster.shared::cluster.b64 _, [rb];\n\t}"
                :: "r"(mbar_addr), "r"(peer) : "memory");
            __stcs(&outn[(size_t)t * RNN_H + gcol], hn);      // overwrite xW slot
            xw_cur = xw_nxt;
        }
        __syncthreads();   // local h-half visible; Psm reusable
        cur ^= 1;
    }

    // keep SMEM alive until peer's in-flight remote stores/arrives complete
    asm volatile("barrier.cluster.arrive.aligned;" ::: "memory");
    asm volatile("barrier.cluster.wait.aligned;" ::: "memory");
}

// ---------------------------------------------------------------------------
extern "C" void kernel_launch(void* const* d_in, const int* in_sizes, int n_in,
                              void* d_out, int out_size) {
    const float* x  = (const float*)d_in[0];   // [N,T,D]
    const float* h0 = (const float*)d_in[1];   // [N,H]
    const float* Wx = (const float*)d_in[2];   // [D,H]
    const float* Wh = (const float*)d_in[3];   // [H,H]
    const float* b  = (const float*)d_in[4];   // [H]
    float* out = (float*)d_out;                // [N,T,H]

    (void)in_sizes; (void)n_in; (void)out_size;

    dim3 g1((RNN_N * RNN_T) / 128, RNN_H / 128);
    gemm_xw_kernel<<<g1, 256>>>(x, Wx, b, out);

    rnn_scan_kernel<<<RNN_N * 2, 512>>>(h0, Wh, out);
}

// round 7
// speedup vs baseline: 2.7063x; 1.4796x over previous
#include <cuda_runtime.h>
#include <cuda_bf16.h>
#include <cstdint>
#include <cstddef>

// RNN_5188320494079: N=64, T=1024, D=256, H=256, fp32.
// Inputs: x[N,T,D], h0[N,H], Wx[D,H], Wh[H,H], b[H]. Output: [N,T,H].
//
// Kernel 1: Out = x @ Wx + b (packed-f32x2 SGEMM, in-place into d_out).
// Kernel 2: 2-CTA-cluster scan, 128 CTAs (2 per batch). Each CTA owns 128
//   output columns; its 256x128 Wh slice lives in registers (64 regs/thread,
//   packed over row pairs). h halves exchanged per step with st.async +
//   mbarrier complete_tx (single local expect_tx arrival per phase).

#define RNN_N 64
#define RNN_T 1024
#define RNN_D 256
#define RNN_H 256
#define HHALF 128

typedef unsigned long long ull;

// packed {f32,f32} fma: d = a*b + d  (bitwise == two fma.rn.f32)
__device__ __forceinline__ void ffma2(ull& d, ull a, ull b) {
    asm("fma.rn.f32x2 %0, %1, %2, %0;" : "+l"(d) : "l"(a), "l"(b));
}
__device__ __forceinline__ float2 u2f(ull u) {
    float2 f;
    asm("mov.b64 {%0, %1}, %2;" : "=f"(f.x), "=f"(f.y) : "l"(u));
    return f;
}
__device__ __forceinline__ ull f2u(float a, float b) {
    ull u;
    asm("mov.b64 %0, {%1, %2};" : "=l"(u) : "f"(a), "f"(b));
    return u;
}
__device__ __forceinline__ uint32_t smem_u32(const void* p) {
    uint32_t a;
    asm("{ .reg .u64 t; cvta.to.shared.u64 t, %1; cvt.u32.u64 %0, t; }"
        : "=r"(a) : "l"(p));
    return a;
}

// ---------------------------------------------------------------------------
// Kernel 1: smem-tiled SGEMM, BM=128 BN=128 BK=16, 256 thr, f32x2 micro-kernel.
// (unchanged from R6 — ~150us, FFMA-bound)
// ---------------------------------------------------------------------------
__global__ __launch_bounds__(256, 2)
void gemm_xw_kernel(const float* __restrict__ X, const float* __restrict__ Wx,
                    const float* __restrict__ bias, float* __restrict__ Out) {
    __shared__ __align__(16) float2 Asd[16][128];
    __shared__ __align__(16) float  Bs[16][128];

    const int tid = threadIdx.x;
    const int tx = tid & 15;
    const int ty = tid >> 4;
    const int m0 = blockIdx.x * 128;
    const int n0 = blockIdx.y * 128;

    const int a_row = tid >> 2;
    const int a_col = (tid & 3) << 2;
    const int b_row = tid >> 5;
    const int b_col = (tid & 31) << 2;

    ull acc[8][4];
#pragma unroll
    for (int i = 0; i < 8; i++)
#pragma unroll
        for (int j = 0; j < 4; j++) acc[i][j] = 0ull;

    const float* Xa0 = &X[(size_t)(m0 + a_row) * RNN_D + a_col];
    const float* Xa1 = &X[(size_t)(m0 + a_row + 64) * RNN_D + a_col];
    const float* Wb0 = &Wx[(size_t)b_row * RNN_H + n0 + b_col];
    const float* Wb1 = &Wx[(size_t)(b_row + 8) * RNN_H + n0 + b_col];

    for (int k0 = 0; k0 < RNN_D; k0 += 16) {
        float4 av0 = __ldcs(reinterpret_cast<const float4*>(Xa0 + k0));
        float4 av1 = __ldcs(reinterpret_cast<const float4*>(Xa1 + k0));
        float4 bv0 = *reinterpret_cast<const float4*>(Wb0 + (size_t)k0 * RNN_H);
        float4 bv1 = *reinterpret_cast<const float4*>(Wb1 + (size_t)k0 * RNN_H);
        __syncthreads();
        Asd[a_col + 0][a_row] = make_float2(av0.x, av0.x);
        Asd[a_col + 1][a_row] = make_float2(av0.y, av0.y);
        Asd[a_col + 2][a_row] = make_float2(av0.z, av0.z);
        Asd[a_col + 3][a_row] = make_float2(av0.w, av0.w);
        Asd[a_col + 0][a_row + 64] = make_float2(av1.x, av1.x);
        Asd[a_col + 1][a_row + 64] = make_float2(av1.y, av1.y);
        Asd[a_col + 2][a_row + 64] = make_float2(av1.z, av1.z);
        Asd[a_col + 3][a_row + 64] = make_float2(av1.w, av1.w);
        *reinterpret_cast<float4*>(&Bs[b_row][b_col]) = bv0;
        *reinterpret_cast<float4*>(&Bs[b_row + 8][b_col]) = bv1;
        __syncthreads();
#pragma unroll
        for (int k = 0; k < 16; k++) {
            const ulonglong2* ad = reinterpret_cast<const ulonglong2*>(&Asd[k][ty * 8]);
            ulonglong2 aa0 = ad[0], aa1 = ad[1], aa2 = ad[2], aa3 = ad[3];
            const ulonglong2* bd = reinterpret_cast<const ulonglong2*>(&Bs[k][tx * 8]);
            ulonglong2 bb0 = bd[0], bb1 = bd[1];
            ull ap[8] = {aa0.x, aa0.y, aa1.x, aa1.y, aa2.x, aa2.y, aa3.x, aa3.y};
            ull bp[4] = {bb0.x, bb0.y, bb1.x, bb1.y};
#pragma unroll
            for (int i = 0; i < 8; i++) {
                ffma2(acc[i][0], ap[i], bp[0]);
                ffma2(acc[i][1], ap[i], bp[1]);
                ffma2(acc[i][2], ap[i], bp[2]);
                ffma2(acc[i][3], ap[i], bp[3]);
            }
        }
    }

    float4 bb0 = *reinterpret_cast<const float4*>(&bias[n0 + tx * 8]);
    float4 bb1 = *reinterpret_cast<const float4*>(&bias[n0 + tx * 8 + 4]);
    float bb[8] = {bb0.x, bb0.y, bb0.z, bb0.w, bb1.x, bb1.y, bb1.z, bb1.w};
#pragma unroll
    for (int i = 0; i < 8; i++) {
        size_t r = (size_t)(m0 + ty * 8 + i) * RNN_H + n0 + tx * 8;
        float2 v0 = u2f(acc[i][0]), v1 = u2f(acc[i][1]);
        float2 v2 = u2f(acc[i][2]), v3 = u2f(acc[i][3]);
        float4 o0 = make_float4(v0.x + bb[0], v0.y + bb[1], v1.x + bb[2], v1.y + bb[3]);
        float4 o1 = make_float4(v2.x + bb[4], v2.y + bb[5], v3.x + bb[6], v3.y + bb[7]);
        *reinterpret_cast<float4*>(&Out[r]) = o0;
        *reinterpret_cast<float4*>(&Out[r + 4]) = o1;
    }
}

// ---------------------------------------------------------------------------
// Kernel 2: cluster scan. Grid 128 CTAs, cluster (2,1,1): cluster = batch n,
// rank r owns output cols [r*128, r*128+128).
// Thread layout (512 thr): col = tid&127, q = tid>>7 (4 row-splits of 64).
// Per thread: Wh[64 rows x 1 col] as 32 packed row-pairs (64 regs).
// Accumulate packed over row pairs: a = {h_i, h_i+1} straight from plain
// smem h buffer (no duplication). 4 partials -> Psm -> 128 finalize threads:
// reduce + fast tanh + local h store + st.async(h) to peer with complete_tx.
// One expecter thread per CTA does mbarrier.arrive.expect_tx(512B) per phase.
// ---------------------------------------------------------------------------
__global__ __launch_bounds__(512, 1) __cluster_dims__(2, 1, 1)
void rnn_scan_kernel(const float* __restrict__ h0,
                     const float* __restrict__ Wh,
                     float* Out) {
    __shared__ __align__(16) float hbuf[2][RNN_H];   // plain h, 2KB
    __shared__ __align__(16) float Psm[4][HHALF];    // partials, 2KB
    __shared__ __align__(8)  unsigned long long mbar;

    const int tid = threadIdx.x;
    uint32_t rank;
    asm("mov.u32 %0, %%cluster_ctarank;" : "=r"(rank));
    const uint32_t peer = rank ^ 1u;
    const int n = blockIdx.x >> 1;
    const int col = tid & 127;
    const int q = tid >> 7;              // 0..3, warp-uniform
    const int ibase = q * 64;
    const int j = (int)rank * HHALF + col;      // my Wh column
    // rows [0,128) produced by rank 0, [128,256) by rank 1
    const bool needs_peer = ((uint32_t)(ibase >> 7) != rank);
    const int expecter = (rank == 0) ? 256 : 0; // a needs_peer thread

    const uint32_t mbar_addr = smem_u32((const void*)&mbar);

    if (tid == 0)
        asm volatile("mbarrier.init.shared.b64 [%0], %1;"
                     :: "r"(mbar_addr), "r"(1) : "memory");

    // Register Wh slice: 32 packed row pairs {Wh[ibase+2k][j], Wh[ibase+2k+1][j]}
    ull wp[32];
#pragma unroll
    for (int k = 0; k < 32; k++) {
        float w0 = __ldg(&Wh[(size_t)(ibase + 2 * k) * RNN_H + j]);
        float w1 = __ldg(&Wh[(size_t)(ibase + 2 * k + 1) * RNN_H + j]);
        wp[k] = f2u(w0, w1);
    }

    float* outn = Out + (size_t)n * RNN_T * RNN_H;
    const int gcol = (int)rank * HHALF + tid;   // output column (tid<128)
    float xw_cur = 0.f, xw_nxt = 0.f;
    if (tid < RNN_H)
        hbuf[0][tid] = h0[(size_t)n * RNN_H + tid];   // full h0 locally

    uint32_t rh0 = 0, rh1 = 0, rmb = 0;
    if (tid < HHALF) {
        xw_cur = __ldcg(&outn[gcol]);
        uint32_t l0 = smem_u32(&hbuf[0][gcol]);
        uint32_t l1 = smem_u32(&hbuf[1][gcol]);
        asm("mapa.shared::cluster.u32 %0, %1, %2;" : "=r"(rh0) : "r"(l0), "r"(peer));
        asm("mapa.shared::cluster.u32 %0, %1, %2;" : "=r"(rh1) : "r"(l1), "r"(peer));
        asm("mapa.shared::cluster.u32 %0, %1, %2;" : "=r"(rmb) : "r"(mbar_addr), "r"(peer));
    }
    __syncthreads();
    // all mbarriers initialized cluster-wide before any remote tx
    asm volatile("barrier.cluster.arrive.aligned;" ::: "memory");
    asm volatile("barrier.cluster.wait.aligned;" ::: "memory");

    // expect for completion #1 (peer's step-0 sends): 128 * 4 bytes
    if (tid == expecter)
        asm volatile("mbarrier.arrive.expect_tx.shared::cta.b64 _, [%0], %1;"
                     :: "r"(mbar_addr), "r"(512u) : "memory");

    int cur = 0;
    for (int t = 0; t < RNN_T; t++) {
        if (tid < HHALF && t + 1 < RNN_T)
            xw_nxt = __ldcg(&outn[(size_t)(t + 1) * RNN_H + gcol]);

        // wait for peer h-half (exchange #t); own-half warps skip -> overlap
        if (needs_peer && t > 0) {
            uint32_t par = (uint32_t)(t - 1) & 1u;
            asm volatile(
                "{\n\t.reg .pred P;\n\t"
                "WL%=:\n\t"
                "mbarrier.try_wait.parity.acquire.cta.shared::cta.b64 P, [%0], %1, 0x989680;\n\t"
                "@P bra.uni WD%=;\n\t"
                "bra.uni WL%=;\n\t"
                "WD%=:\n\t}"
                :: "r"(mbar_addr), "r"(par) : "memory");
        }
        // expect for next completion (#t+1); safe: expecter just observed #t
        if (t > 0 && t + 1 < RNN_T && tid == expecter)
            asm volatile("mbarrier.arrive.expect_tx.shared::cta.b64 _, [%0], %1;"
                         :: "r"(mbar_addr), "r"(512u) : "memory");

        // 32 packed FFMA2 over row pairs; a-operand = natural {h_i, h_i+1}
        const ulonglong2* hp =
            reinterpret_cast<const ulonglong2*>(&hbuf[cur][ibase]);
        ull acc0 = 0ull, acc1 = 0ull;
#pragma unroll
        for (int m = 0; m < 16; m++) {
            ulonglong2 hv = hp[m];          // broadcast LDS.128: 4 h values
            ffma2(acc0, hv.x, wp[2 * m]);
            ffma2(acc1, hv.y, wp[2 * m + 1]);
        }
        float2 f0 = u2f(acc0), f1 = u2f(acc1);
        Psm[q][col] = (f0.x + f0.y) + (f1.x + f1.y);
        __syncthreads();

        const int nxt = cur ^ 1;
        if (tid < HHALF) {
            float z = xw_cur + ((Psm[0][tid] + Psm[1][tid]) +
                                (Psm[2][tid] + Psm[3][tid]));
            // tanh(z) = 1 - 2/(e^{2z}+1); MUFU-based, ~1e-6 rel err
            float e = __expf(2.0f * z);
            float hn = 1.0f - __fdividef(2.0f, e + 1.0f);
            hbuf[nxt][gcol] = hn;                         // local copy
            if (t + 1 < RNN_T) {                          // peer copy + tx signal
                uint32_t ra = nxt ? rh1 : rh0;
                asm volatile(
                    "st.async.shared::cluster.mbarrier::complete_tx::bytes.b32 [%0], %1, [%2];"
                    :: "r"(ra), "f"(hn), "r"(rmb) : "memory");
            }
            __stcs(&outn[(size_t)t * RNN_H + gcol], hn);  // overwrite xW slot
            xw_cur = xw_nxt;
        }
        __syncthreads();   // local h-half visible; Psm reusable
        cur ^= 1;
    }

    // keep SMEM alive until all remote traffic has drained cluster-wide
    asm volatile("barrier.cluster.arrive.aligned;" ::: "memory");
    asm volatile("barrier.cluster.wait.aligned;" ::: "memory");
}

// ---------------------------------------------------------------------------
extern "C" void kernel_launch(void* const* d_in, const int* in_sizes, int n_in,
                              void* d_out, int out_size) {
    const float* x  = (const float*)d_in[0];   // [N,T,D]
    const float* h0 = (const float*)d_in[1];   // [N,H]
    const float* Wx = (const float*)d_in[2];   // [D,H]
    const float* Wh = (const float*)d_in[3];   // [H,H]
    const float* b  = (const float*)d_in[4];   // [H]
    float* out = (float*)d_out;                // [N,T,H]

    (void)in_sizes; (void)n_in; (void)out_size;

    dim3 g1((RNN_N * RNN_T) / 128, RNN_H / 128);
    gemm_xw_kernel<<<g1, 256>>>(x, Wx, b, out);

    rnn_scan_kernel<<<RNN_N * 2, 512>>>(h0, Wh, out);
}